// round 3
// baseline (speedup 1.0000x reference)
#include <cuda_runtime.h>

// Problem constants
#define BB 4
#define SS 1024
#define EE 2048
#define HH 32
#define DD 64
#define MM 4096   // BB*SS

// ---------------- device scratch (allocation-free rule: __device__ globals) ----------------
__device__ float g_q[BB*HH*SS*DD];            // (B,H,S,D)  33.5 MB
__device__ float g_k[BB*HH*SS*DD];
__device__ float g_v[BB*HH*SS*DD];
__device__ float g_ctx[MM*EE];                // (B,S,E)    33.5 MB
__device__ float g_scores[134217728];         // (B*H,S,S)  512 MB

// ---------------- packed f32x2 helpers (sm_103a FFMA2 pipe) ----------------
__device__ __forceinline__ unsigned long long dup2(float a) {
    unsigned long long r;
    asm("mov.b64 %0, {%1, %1};" : "=l"(r) : "f"(a));
    return r;
}
__device__ __forceinline__ unsigned long long fma2(unsigned long long a, unsigned long long b,
                                                   unsigned long long c) {
    unsigned long long d;
    asm("fma.rn.f32x2 %0, %1, %2, %3;" : "=l"(d) : "l"(a), "l"(b), "l"(c));
    return d;
}
__device__ __forceinline__ float2 unpack2(unsigned long long v) {
    float lo, hi;
    asm("mov.b64 {%0, %1}, %2;" : "=f"(lo), "=f"(hi) : "l"(v));
    return make_float2(lo, hi);
}

// =====================================================================================
// Kernel 1: fused Q/K/V projection.  C = hidden @ W^T + bias (scaled for Q),
// scattered to (B,H,S,D).  Tile 128x128x8, 256 threads, 8x8 per-thread via f32x2.
// Double-buffered smem: prefetch next k-tile to regs, compute current, store, 1 BAR/iter.
// grid (E/128=16, M/128=32, 3)
// =====================================================================================
__global__ __launch_bounds__(256, 2)
void qkv_kernel(const float* __restrict__ hidden,
                const float* __restrict__ Wq, const float* __restrict__ bq,
                const float* __restrict__ Wk, const float* __restrict__ bk,
                const float* __restrict__ Wv, const float* __restrict__ bv)
{
    __shared__ __align__(16) float As[2][8][128];
    __shared__ __align__(16) float Bs[2][8][128];

    const int t  = threadIdx.x;
    const int bx = blockIdx.x, by = blockIdx.y, z = blockIdx.z;

    const float* W    = (z == 0) ? Wq : (z == 1) ? Wk : Wv;
    const float* bias = (z == 0) ? bq : (z == 1) ? bk : bv;
    float*       outp = (z == 0) ? g_q : (z == 1) ? g_k : g_v;
    const float scale = (z == 0) ? 0.125f : 1.0f;   // D^-0.5 = 1/8

    const int loadRow = t >> 1;
    const int loadCol = (t & 1) * 4;
    const float* Aptr = hidden + (size_t)(by * 128 + loadRow) * EE + loadCol;
    const float* Wptr = W      + (size_t)(bx * 128 + loadRow) * EE + loadCol;

    const int ty = t >> 4, tx = t & 15;

    unsigned long long acc[8][4];
#pragma unroll
    for (int i = 0; i < 8; i++)
#pragma unroll
        for (int p = 0; p < 4; p++) acc[i][p] = 0ULL;

    // preload tile 0 into buffer 0
    {
        float4 av = *(const float4*)(Aptr);
        float4 wv = *(const float4*)(Wptr);
        As[0][loadCol + 0][loadRow] = av.x;
        As[0][loadCol + 1][loadRow] = av.y;
        As[0][loadCol + 2][loadRow] = av.z;
        As[0][loadCol + 3][loadRow] = av.w;
        Bs[0][loadCol + 0][loadRow] = wv.x;
        Bs[0][loadCol + 1][loadRow] = wv.y;
        Bs[0][loadCol + 2][loadRow] = wv.z;
        Bs[0][loadCol + 3][loadRow] = wv.w;
    }
    __syncthreads();

#pragma unroll 1
    for (int k0 = 0; k0 < EE; k0 += 8) {
        const int buf = (k0 >> 3) & 1;
        float4 av2, wv2;
        const bool more = (k0 + 8) < EE;
        if (more) {
            av2 = *(const float4*)(Aptr + k0 + 8);
            wv2 = *(const float4*)(Wptr + k0 + 8);
        }
#pragma unroll
        for (int kk = 0; kk < 8; kk++) {
            float4 a0 = *(const float4*)&As[buf][kk][ty * 8];
            float4 a1 = *(const float4*)&As[buf][kk][ty * 8 + 4];
            ulonglong2 b0 = *(const ulonglong2*)&Bs[buf][kk][tx * 8];
            ulonglong2 b1 = *(const ulonglong2*)&Bs[buf][kk][tx * 8 + 4];
            float a[8] = {a0.x, a0.y, a0.z, a0.w, a1.x, a1.y, a1.z, a1.w};
#pragma unroll
            for (int i = 0; i < 8; i++) {
                unsigned long long ad = dup2(a[i]);
                acc[i][0] = fma2(ad, b0.x, acc[i][0]);
                acc[i][1] = fma2(ad, b0.y, acc[i][1]);
                acc[i][2] = fma2(ad, b1.x, acc[i][2]);
                acc[i][3] = fma2(ad, b1.y, acc[i][3]);
            }
        }
        if (more) {
            const int nb = buf ^ 1;
            As[nb][loadCol + 0][loadRow] = av2.x;
            As[nb][loadCol + 1][loadRow] = av2.y;
            As[nb][loadCol + 2][loadRow] = av2.z;
            As[nb][loadCol + 3][loadRow] = av2.w;
            Bs[nb][loadCol + 0][loadRow] = wv2.x;
            Bs[nb][loadCol + 1][loadRow] = wv2.y;
            Bs[nb][loadCol + 2][loadRow] = wv2.z;
            Bs[nb][loadCol + 3][loadRow] = wv2.w;
        }
        __syncthreads();
    }

    const int row0 = by * 128 + ty * 8;
    const int col0 = bx * 128 + tx * 8;
#pragma unroll
    for (int i = 0; i < 8; i++) {
        int r = row0 + i;
        int b = r >> 10, s = r & 1023;
#pragma unroll
        for (int p = 0; p < 4; p++) {
            float2 v = unpack2(acc[i][p]);
            int c = col0 + p * 2;
            int h = c >> 6, d = c & 63;   // c..c+1 stay inside one head (8-aligned groups)
            size_t base = (((size_t)(b * HH + h)) * SS + s) * DD + d;
            outp[base]     = (v.x + bias[c])     * scale;
            outp[base + 1] = (v.y + bias[c + 1]) * scale;
        }
    }
}

// =====================================================================================
// Kernel 2: scores[bh] = Q[bh] @ K[bh]^T + mask[b].   K-dim = D = 64.
// grid (S/128=8, S/128=8, B*H=128), 256 threads.
// =====================================================================================
__global__ __launch_bounds__(256, 2)
void scores_kernel(const float* __restrict__ mask)
{
    __shared__ __align__(16) float As[8][128];
    __shared__ __align__(16) float Bs[8][128];

    const int t  = threadIdx.x;
    const int bx = blockIdx.x, by = blockIdx.y, z = blockIdx.z;   // z = b*H + h
    const int b  = z >> 5;

    const float* Qb = g_q + (size_t)z * SS * DD;
    const float* Kb = g_k + (size_t)z * SS * DD;

    const int loadRow = t >> 1;
    const int loadCol = (t & 1) * 4;
    const float* Aptr = Qb + (size_t)(by * 128 + loadRow) * DD + loadCol;
    const float* Bptr = Kb + (size_t)(bx * 128 + loadRow) * DD + loadCol;

    const int ty = t >> 4, tx = t & 15;

    unsigned long long acc[8][4];
#pragma unroll
    for (int i = 0; i < 8; i++)
#pragma unroll
        for (int p = 0; p < 4; p++) acc[i][p] = 0ULL;

#pragma unroll 1
    for (int k0 = 0; k0 < DD; k0 += 8) {
        float4 av = *(const float4*)(Aptr + k0);
        float4 bv = *(const float4*)(Bptr + k0);
        As[loadCol + 0][loadRow] = av.x;
        As[loadCol + 1][loadRow] = av.y;
        As[loadCol + 2][loadRow] = av.z;
        As[loadCol + 3][loadRow] = av.w;
        Bs[loadCol + 0][loadRow] = bv.x;
        Bs[loadCol + 1][loadRow] = bv.y;
        Bs[loadCol + 2][loadRow] = bv.z;
        Bs[loadCol + 3][loadRow] = bv.w;
        __syncthreads();
#pragma unroll
        for (int kk = 0; kk < 8; kk++) {
            float4 a0 = *(const float4*)&As[kk][ty * 8];
            float4 a1 = *(const float4*)&As[kk][ty * 8 + 4];
            ulonglong2 b0 = *(const ulonglong2*)&Bs[kk][tx * 8];
            ulonglong2 b1 = *(const ulonglong2*)&Bs[kk][tx * 8 + 4];
            float a[8] = {a0.x, a0.y, a0.z, a0.w, a1.x, a1.y, a1.z, a1.w};
#pragma unroll
            for (int i = 0; i < 8; i++) {
                unsigned long long ad = dup2(a[i]);
                acc[i][0] = fma2(ad, b0.x, acc[i][0]);
                acc[i][1] = fma2(ad, b0.y, acc[i][1]);
                acc[i][2] = fma2(ad, b1.x, acc[i][2]);
                acc[i][3] = fma2(ad, b1.y, acc[i][3]);
            }
        }
        __syncthreads();
    }

    const int row0 = by * 128 + ty * 8;
    const int col0 = bx * 128 + tx * 8;
    const float* mrow = mask + (size_t)b * SS * SS;
    float* srow = g_scores + (size_t)z * SS * SS;
#pragma unroll
    for (int i = 0; i < 8; i++) {
        size_t roff = (size_t)(row0 + i) * SS;
#pragma unroll
        for (int p = 0; p < 4; p++) {
            float2 v = unpack2(acc[i][p]);
            int c = col0 + p * 2;
            srow[roff + c]     = v.x + mrow[roff + c];
            srow[roff + c + 1] = v.y + mrow[roff + c + 1];
        }
    }
}

// =====================================================================================
// Kernel 3: row softmax over S=1024, in place.  grid = B*H*S = 131072, 256 threads.
// =====================================================================================
__global__ __launch_bounds__(256)
void softmax_kernel()
{
    __shared__ float red[256];
    const int t = threadIdx.x;
    float* row = g_scores + (size_t)blockIdx.x * SS;

    float4 v = ((const float4*)row)[t];
    float m = fmaxf(fmaxf(v.x, v.y), fmaxf(v.z, v.w));
    red[t] = m;
    __syncthreads();
    for (int s = 128; s > 0; s >>= 1) {
        if (t < s) red[t] = fmaxf(red[t], red[t + s]);
        __syncthreads();
    }
    const float mx = red[0];
    __syncthreads();

    float4 e;
    e.x = expf(v.x - mx);
    e.y = expf(v.y - mx);
    e.z = expf(v.z - mx);
    e.w = expf(v.w - mx);
    red[t] = e.x + e.y + e.z + e.w;
    __syncthreads();
    for (int s = 128; s > 0; s >>= 1) {
        if (t < s) red[t] += red[t + s];
        __syncthreads();
    }
    const float inv = 1.0f / red[0];

    e.x *= inv; e.y *= inv; e.z *= inv; e.w *= inv;
    ((float4*)row)[t] = e;
}

// =====================================================================================
// Kernel 4: ctx[bh] = P[bh] @ V[bh]  (A @ B, B not transposed; N = D = 64)
// Tile 128x64x8, 128 threads (16x8), 8x8 per thread.  grid (S/128=8, B*H=128).
// Output written to (B,S,E) layout in g_ctx.
// =====================================================================================
__global__ __launch_bounds__(128, 2)
void pv_kernel()
{
    __shared__ __align__(16) float As[8][128];
    __shared__ __align__(16) float Bs[8][64];

    const int t  = threadIdx.x;
    const int by = blockIdx.x, z = blockIdx.y;   // z = b*H + h
    const int b  = z >> 5, h = z & 31;

    const float* P = g_scores + (size_t)z * SS * SS;
    const float* V = g_v      + (size_t)z * SS * DD;

    // A loads: 256 float4 over 128 threads -> 2 each
    const int r0  = t >> 1;
    const int cg  = (t & 1) * 4;
    // B loads: 128 float4, 1 each
    const int bkr = t >> 4;                 // 0..7
    const int bkc = (t & 15) * 4;

    const int ty = t >> 3, tx = t & 7;

    unsigned long long acc[8][4];
#pragma unroll
    for (int i = 0; i < 8; i++)
#pragma unroll
        for (int p = 0; p < 4; p++) acc[i][p] = 0ULL;

    for (int k0 = 0; k0 < SS; k0 += 8) {
        float4 a0 = *(const float4*)(P + (size_t)(by * 128 + r0) * SS + k0 + cg);
        float4 a1 = *(const float4*)(P + (size_t)(by * 128 + 64 + r0) * SS + k0 + cg);
        As[cg + 0][r0] = a0.x;  As[cg + 1][r0] = a0.y;
        As[cg + 2][r0] = a0.z;  As[cg + 3][r0] = a0.w;
        As[cg + 0][64 + r0] = a1.x;  As[cg + 1][64 + r0] = a1.y;
        As[cg + 2][64 + r0] = a1.z;  As[cg + 3][64 + r0] = a1.w;
        float4 bv = *(const float4*)(V + (size_t)(k0 + bkr) * DD + bkc);
        *(float4*)&Bs[bkr][bkc] = bv;
        __syncthreads();
#pragma unroll
        for (int kk = 0; kk < 8; kk++) {
            float4 av0 = *(const float4*)&As[kk][ty * 8];
            float4 av1 = *(const float4*)&As[kk][ty * 8 + 4];
            ulonglong2 b0 = *(const ulonglong2*)&Bs[kk][tx * 8];
            ulonglong2 b1 = *(const ulonglong2*)&Bs[kk][tx * 8 + 4];
            float a[8] = {av0.x, av0.y, av0.z, av0.w, av1.x, av1.y, av1.z, av1.w};
#pragma unroll
            for (int i = 0; i < 8; i++) {
                unsigned long long ad = dup2(a[i]);
                acc[i][0] = fma2(ad, b0.x, acc[i][0]);
                acc[i][1] = fma2(ad, b0.y, acc[i][1]);
                acc[i][2] = fma2(ad, b1.x, acc[i][2]);
                acc[i][3] = fma2(ad, b1.y, acc[i][3]);
            }
        }
        __syncthreads();
    }

    const int row0 = by * 128 + ty * 8;
    const int col0 = tx * 8;               // d index within head
#pragma unroll
    for (int i = 0; i < 8; i++) {
        int q = row0 + i;
        float* orow = g_ctx + ((size_t)(b * SS + q)) * EE + h * DD;
#pragma unroll
        for (int p = 0; p < 4; p++) {
            float2 v = unpack2(acc[i][p]);
            int c = col0 + p * 2;
            orow[c]     = v.x;
            orow[c + 1] = v.y;
        }
    }
}

// =====================================================================================
// Kernel 5: out = ctx @ Wo^T + bo  -> d_out (B,S,E) row-major.
// Double-buffered like kernel 1.  grid (16, 32), 256 threads.
// =====================================================================================
__global__ __launch_bounds__(256, 2)
void outproj_kernel(const float* __restrict__ Wo, const float* __restrict__ bo,
                    float* __restrict__ out)
{
    __shared__ __align__(16) float As[2][8][128];
    __shared__ __align__(16) float Bs[2][8][128];

    const int t  = threadIdx.x;
    const int bx = blockIdx.x, by = blockIdx.y;

    const int loadRow = t >> 1;
    const int loadCol = (t & 1) * 4;
    const float* Aptr = g_ctx + (size_t)(by * 128 + loadRow) * EE + loadCol;
    const float* Wptr = Wo    + (size_t)(bx * 128 + loadRow) * EE + loadCol;

    const int ty = t >> 4, tx = t & 15;

    unsigned long long acc[8][4];
#pragma unroll
    for (int i = 0; i < 8; i++)
#pragma unroll
        for (int p = 0; p < 4; p++) acc[i][p] = 0ULL;

    {
        float4 av = *(const float4*)(Aptr);
        float4 wv = *(const float4*)(Wptr);
        As[0][loadCol + 0][loadRow] = av.x;
        As[0][loadCol + 1][loadRow] = av.y;
        As[0][loadCol + 2][loadRow] = av.z;
        As[0][loadCol + 3][loadRow] = av.w;
        Bs[0][loadCol + 0][loadRow] = wv.x;
        Bs[0][loadCol + 1][loadRow] = wv.y;
        Bs[0][loadCol + 2][loadRow] = wv.z;
        Bs[0][loadCol + 3][loadRow] = wv.w;
    }
    __syncthreads();

#pragma unroll 1
    for (int k0 = 0; k0 < EE; k0 += 8) {
        const int buf = (k0 >> 3) & 1;
        float4 av2, wv2;
        const bool more = (k0 + 8) < EE;
        if (more) {
            av2 = *(const float4*)(Aptr + k0 + 8);
            wv2 = *(const float4*)(Wptr + k0 + 8);
        }
#pragma unroll
        for (int kk = 0; kk < 8; kk++) {
            float4 a0 = *(const float4*)&As[buf][kk][ty * 8];
            float4 a1 = *(const float4*)&As[buf][kk][ty * 8 + 4];
            ulonglong2 b0 = *(const ulonglong2*)&Bs[buf][kk][tx * 8];
            ulonglong2 b1 = *(const ulonglong2*)&Bs[buf][kk][tx * 8 + 4];
            float a[8] = {a0.x, a0.y, a0.z, a0.w, a1.x, a1.y, a1.z, a1.w};
#pragma unroll
            for (int i = 0; i < 8; i++) {
                unsigned long long ad = dup2(a[i]);
                acc[i][0] = fma2(ad, b0.x, acc[i][0]);
                acc[i][1] = fma2(ad, b0.y, acc[i][1]);
                acc[i][2] = fma2(ad, b1.x, acc[i][2]);
                acc[i][3] = fma2(ad, b1.y, acc[i][3]);
            }
        }
        if (more) {
            const int nb = buf ^ 1;
            As[nb][loadCol + 0][loadRow] = av2.x;
            As[nb][loadCol + 1][loadRow] = av2.y;
            As[nb][loadCol + 2][loadRow] = av2.z;
            As[nb][loadCol + 3][loadRow] = av2.w;
            Bs[nb][loadCol + 0][loadRow] = wv2.x;
            Bs[nb][loadCol + 1][loadRow] = wv2.y;
            Bs[nb][loadCol + 2][loadRow] = wv2.z;
            Bs[nb][loadCol + 3][loadRow] = wv2.w;
        }
        __syncthreads();
    }

    const int row0 = by * 128 + ty * 8;
    const int col0 = bx * 128 + tx * 8;
#pragma unroll
    for (int i = 0; i < 8; i++) {
        float* orow = out + (size_t)(row0 + i) * EE;
#pragma unroll
        for (int p = 0; p < 4; p++) {
            float2 v = unpack2(acc[i][p]);
            int c = col0 + p * 2;
            orow[c]     = v.x + bo[c];
            orow[c + 1] = v.y + bo[c + 1];
        }
    }
}

// =====================================================================================
// kernel_launch — metadata order: hidden_states, attention_mask, Wq, bq, Wk, bk,
//                                 Wv, bv, Wo, bo
// =====================================================================================
extern "C" void kernel_launch(void* const* d_in, const int* in_sizes, int n_in,
                              void* d_out, int out_size)
{
    const float* hidden = (const float*)d_in[0];
    const float* mask   = (const float*)d_in[1];
    const float* Wq     = (const float*)d_in[2];
    const float* bq     = (const float*)d_in[3];
    const float* Wk     = (const float*)d_in[4];
    const float* bk     = (const float*)d_in[5];
    const float* Wv     = (const float*)d_in[6];
    const float* bv     = (const float*)d_in[7];
    const float* Wo     = (const float*)d_in[8];
    const float* bo     = (const float*)d_in[9];
    float*       out    = (float*)d_out;

    qkv_kernel<<<dim3(EE / 128, MM / 128, 3), 256>>>(hidden, Wq, bq, Wk, bk, Wv, bv);
    scores_kernel<<<dim3(SS / 128, SS / 128, BB * HH), 256>>>(mask);
    softmax_kernel<<<BB * HH * SS, 256>>>();
    pv_kernel<<<dim3(SS / 128, BB * HH), 128>>>();
    outproj_kernel<<<dim3(EE / 128, MM / 128), 256>>>(Wo, bo, out);
}

// round 6
// speedup vs baseline: 1.3847x; 1.3847x over previous
#include <cuda_runtime.h>
#include <cuda_bf16.h>

// Problem constants
#define BB 4
#define SS 1024
#define EE 2048
#define HH 32
#define DD 64
#define MM 4096   // BB*SS

// ---------------- device scratch (allocation-free rule: __device__ globals) ----------------
__device__ float g_q[BB*HH*SS*DD];            // (B,H,S,D)
__device__ float g_k[BB*HH*SS*DD];
__device__ float g_v[BB*HH*SS*DD];
__device__ float g_ctx[MM*EE];                // (B,S,E)
__device__ float g_scores[134217728];         // (B*H,S,S)
// split-bf16 planes (bit patterns held as ushort)
__device__ __align__(16) unsigned short g_hidh[MM*EE], g_hidl[MM*EE];
__device__ __align__(16) unsigned short g_wh[4*EE*EE], g_wl[4*EE*EE];
__device__ __align__(16) unsigned short g_ctxh[MM*EE], g_ctxl[MM*EE];

// ---------------- packed f32x2 helpers (attention-middle kernels) ----------------
__device__ __forceinline__ unsigned long long dup2(float a) {
    unsigned long long r;
    asm("mov.b64 %0, {%1, %1};" : "=l"(r) : "f"(a));
    return r;
}
__device__ __forceinline__ unsigned long long fma2(unsigned long long a, unsigned long long b,
                                                   unsigned long long c) {
    unsigned long long d;
    asm("fma.rn.f32x2 %0, %1, %2, %3;" : "=l"(d) : "l"(a), "l"(b), "l"(c));
    return d;
}
__device__ __forceinline__ float2 unpack2(unsigned long long v) {
    float lo, hi;
    asm("mov.b64 {%0, %1}, %2;" : "=f"(lo), "=f"(hi) : "l"(v));
    return make_float2(lo, hi);
}

// ---------------- bf16 bit helpers ----------------
__device__ __forceinline__ unsigned short f2bf(float x) {
    unsigned short r;
    asm("cvt.rn.bf16.f32 %0, %1;" : "=h"(r) : "f"(x));
    return r;
}
__device__ __forceinline__ float bf2f(unsigned short u) {
    return __uint_as_float(((unsigned)u) << 16);
}
__device__ __forceinline__ unsigned smem_u32(const void* p) {
    unsigned a;
    asm("{ .reg .u64 t; cvta.to.shared.u64 t, %1; cvt.u32.u64 %0, t; }" : "=r"(a) : "l"(p));
    return a;
}

// ---------------- mma.sync / ldmatrix (family-common, works at sm_103 target) ----------------
#define LDSM4(r0, r1, r2, r3, addr)                                             \
    asm volatile("ldmatrix.sync.aligned.m8n8.x4.shared.b16 {%0,%1,%2,%3}, [%4];" \
                 : "=r"(r0), "=r"(r1), "=r"(r2), "=r"(r3) : "r"(addr))

#define MMA16816(d, a0, a1, a2, a3, b0, b1)                                        \
    asm volatile("mma.sync.aligned.m16n8k16.row.col.f32.bf16.bf16.f32 "            \
                 "{%0,%1,%2,%3}, {%4,%5,%6,%7}, {%8,%9}, {%0,%1,%2,%3};"           \
                 : "+f"(d[0]), "+f"(d[1]), "+f"(d[2]), "+f"(d[3])                  \
                 : "r"(a0), "r"(a1), "r"(a2), "r"(a3), "r"(b0), "r"(b1))

// =====================================================================================
// Pre-pass: fp32 -> (hi, lo) bf16 planes.  x = bf16(x) + bf16(x - bf16(x)) + O(u^2).
// =====================================================================================
__global__ __launch_bounds__(256)
void cvt_kernel(const float* __restrict__ src, unsigned short* __restrict__ hi,
                unsigned short* __restrict__ lo, int n4)
{
    int i = blockIdx.x * 256 + threadIdx.x;
    if (i >= n4) return;
    float4 v = ((const float4*)src)[i];
    unsigned short hx = f2bf(v.x), hy = f2bf(v.y), hz = f2bf(v.z), hw = f2bf(v.w);
    unsigned short lx = f2bf(v.x - bf2f(hx)), ly = f2bf(v.y - bf2f(hy));
    unsigned short lz = f2bf(v.z - bf2f(hz)), lw = f2bf(v.w - bf2f(hw));
    ((uint2*)hi)[i] = make_uint2((unsigned)hx | ((unsigned)hy << 16),
                                 (unsigned)hz | ((unsigned)hw << 16));
    ((uint2*)lo)[i] = make_uint2((unsigned)lx | ((unsigned)ly << 16),
                                 (unsigned)lz | ((unsigned)lw << 16));
}

// =====================================================================================
// Tensor-core projection GEMM (mma.sync HMMA path).
// C[128x128] = A[128xK] @ W[128xK]^T via split-bf16 (AhBh + AhBl + AlBh), fp32 accum.
// CTA 128x128, 256 threads = 8 warps (2m x 4n), warp tile 64x32, k-chunk 32.
// flat=0: qkv mode (z selects W/bias; scatter to (B,H,S,D); Q scaled by 1/8).
// flat=1: outproj mode (flat row-major out + bias).
// =====================================================================================
#define SPAD 40   // smem row stride in bf16 elems (128B rows -> conflict-free ldmatrix)

__global__ __launch_bounds__(256, 1)
void mma_proj_kernel(const unsigned short* __restrict__ Ah,
                     const unsigned short* __restrict__ Al,
                     const unsigned short* __restrict__ Whb,
                     const unsigned short* __restrict__ Wlb,
                     const float* __restrict__ b0, const float* __restrict__ b1,
                     const float* __restrict__ b2,
                     float* __restrict__ flat_out, int flat)
{
    __shared__ __align__(16) unsigned short sAh[128 * SPAD], sAl[128 * SPAD];
    __shared__ __align__(16) unsigned short sBh[128 * SPAD], sBl[128 * SPAD];

    const int t    = threadIdx.x;
    const int lane = t & 31;
    const int wid  = t >> 5;
    const int wm   = wid >> 2;          // 0..1
    const int wn   = wid & 3;           // 0..3
    const int bx = blockIdx.x, by = blockIdx.y, z = blockIdx.z;

    const unsigned short* Wh = Whb + (size_t)z * EE * EE;
    const unsigned short* Wl = Wlb + (size_t)z * EE * EE;
    const float* bias = (z == 0) ? b0 : (z == 1) ? b1 : b2;
    float*       outp = (z == 0) ? g_q : (z == 1) ? g_k : g_v;
    const float scale = (flat == 0 && z == 0) ? 0.125f : 1.0f;

    const int m0 = by * 128, n0 = bx * 128;

    float acc[4][4][4];
#pragma unroll
    for (int i = 0; i < 4; i++)
#pragma unroll
        for (int j = 0; j < 4; j++)
#pragma unroll
            for (int p = 0; p < 4; p++) acc[i][j][p] = 0.0f;

    // ldmatrix source addresses (thread-dependent row/col within tile)
    const int a_row = wm * 64 + ((lane >> 3) & 1) * 8 + (lane & 7);
    const int a_co  = ((lane >> 4) & 1) * 8;
    const int b_row = wn * 32 + ((lane >> 4) & 1) * 8 + (lane & 7);
    const int b_co  = ((lane >> 3) & 1) * 8;
    const unsigned aAh = smem_u32(sAh) + (unsigned)((a_row * SPAD + a_co) * 2);
    const unsigned aAl = smem_u32(sAl) + (unsigned)((a_row * SPAD + a_co) * 2);
    const unsigned aBh = smem_u32(sBh) + (unsigned)((b_row * SPAD + b_co) * 2);
    const unsigned aBl = smem_u32(sBl) + (unsigned)((b_row * SPAD + b_co) * 2);

#pragma unroll 1
    for (int ch = 0; ch < EE / 32; ch++) {
        const int k0 = ch * 32;
        // ---- load chunk: 128 rows x 32 bf16 per array; 512 uint4 / array ----
#pragma unroll
        for (int jj = 0; jj < 2; jj++) {
            const int u   = t * 2 + jj;
            const int row = u >> 2;
            const int cq  = (u & 3) * 8;
            const size_t ai = (size_t)(m0 + row) * EE + k0 + cq;
            const size_t bi = (size_t)(n0 + row) * EE + k0 + cq;
            *(uint4*)&sAh[row * SPAD + cq] = *(const uint4*)&Ah[ai];
            *(uint4*)&sAl[row * SPAD + cq] = *(const uint4*)&Al[ai];
            *(uint4*)&sBh[row * SPAD + cq] = *(const uint4*)&Wh[bi];
            *(uint4*)&sBl[row * SPAD + cq] = *(const uint4*)&Wl[bi];
        }
        __syncthreads();

        // ---- compute: two k16 steps ----
#pragma unroll
        for (int kk2 = 0; kk2 < 2; kk2++) {
            const unsigned ko = (unsigned)(kk2 * 16 * 2);
            unsigned ah[4][4], al[4][4], bh[2][4], bl[2][4];
#pragma unroll
            for (int mt = 0; mt < 4; mt++) {
                const unsigned off = (unsigned)(mt * 16 * SPAD * 2) + ko;
                LDSM4(ah[mt][0], ah[mt][1], ah[mt][2], ah[mt][3], aAh + off);
                LDSM4(al[mt][0], al[mt][1], al[mt][2], al[mt][3], aAl + off);
            }
#pragma unroll
            for (int np = 0; np < 2; np++) {
                const unsigned off = (unsigned)(np * 16 * SPAD * 2) + ko;
                LDSM4(bh[np][0], bh[np][1], bh[np][2], bh[np][3], aBh + off);
                LDSM4(bl[np][0], bl[np][1], bl[np][2], bl[np][3], aBl + off);
            }
#pragma unroll
            for (int mt = 0; mt < 4; mt++) {
#pragma unroll
                for (int np = 0; np < 2; np++) {
#pragma unroll
                    for (int hf = 0; hf < 2; hf++) {
                        const int nt = np * 2 + hf;
                        const unsigned B0h = bh[np][hf * 2], B1h = bh[np][hf * 2 + 1];
                        const unsigned B0l = bl[np][hf * 2], B1l = bl[np][hf * 2 + 1];
                        MMA16816(acc[mt][nt], ah[mt][0], ah[mt][1], ah[mt][2], ah[mt][3], B0h, B1h);
                        MMA16816(acc[mt][nt], ah[mt][0], ah[mt][1], ah[mt][2], ah[mt][3], B0l, B1l);
                        MMA16816(acc[mt][nt], al[mt][0], al[mt][1], al[mt][2], al[mt][3], B0h, B1h);
                    }
                }
            }
        }
        __syncthreads();
    }

    // ---- epilogue: D fragment rows = lane>>2 (+8), cols = (lane&3)*2 (+1) ----
    const int erow = lane >> 2;
    const int ecol = (lane & 3) * 2;
#pragma unroll
    for (int mt = 0; mt < 4; mt++) {
#pragma unroll
        for (int nt = 0; nt < 4; nt++) {
            const int m = m0 + wm * 64 + mt * 16 + erow;
            const int n = n0 + wn * 32 + nt * 8 + ecol;
            const float bz0 = bias[n], bz1 = bias[n + 1];
            if (flat) {
                float* p0 = flat_out + (size_t)m * EE + n;
                float* p1 = flat_out + (size_t)(m + 8) * EE + n;
                p0[0] = acc[mt][nt][0] + bz0;
                p0[1] = acc[mt][nt][1] + bz1;
                p1[0] = acc[mt][nt][2] + bz0;
                p1[1] = acc[mt][nt][3] + bz1;
            } else {
                const int h = n >> 6, d = n & 63;
                const int b0i = m >> 10, s0 = m & 1023;
                const int b1i = (m + 8) >> 10, s1 = (m + 8) & 1023;
                float* p0 = outp + ((size_t)(b0i * HH + h) * SS + s0) * DD + d;
                float* p1 = outp + ((size_t)(b1i * HH + h) * SS + s1) * DD + d;
                p0[0] = (acc[mt][nt][0] + bz0) * scale;
                p0[1] = (acc[mt][nt][1] + bz1) * scale;
                p1[0] = (acc[mt][nt][2] + bz0) * scale;
                p1[1] = (acc[mt][nt][3] + bz1) * scale;
            }
        }
    }
}

// =====================================================================================
// Kernel 2: scores[bh] = Q[bh] @ K[bh]^T + mask[b]  (unchanged, passing)
// =====================================================================================
__global__ __launch_bounds__(256, 2)
void scores_kernel(const float* __restrict__ mask)
{
    __shared__ __align__(16) float As[8][128];
    __shared__ __align__(16) float Bs[8][128];

    const int t  = threadIdx.x;
    const int bx = blockIdx.x, by = blockIdx.y, z = blockIdx.z;
    const int b  = z >> 5;

    const float* Qb = g_q + (size_t)z * SS * DD;
    const float* Kb = g_k + (size_t)z * SS * DD;

    const int loadRow = t >> 1;
    const int loadCol = (t & 1) * 4;
    const float* Aptr = Qb + (size_t)(by * 128 + loadRow) * DD + loadCol;
    const float* Bptr = Kb + (size_t)(bx * 128 + loadRow) * DD + loadCol;

    const int ty = t >> 4, tx = t & 15;

    unsigned long long acc[8][4];
#pragma unroll
    for (int i = 0; i < 8; i++)
#pragma unroll
        for (int p = 0; p < 4; p++) acc[i][p] = 0ULL;

#pragma unroll 1
    for (int k0 = 0; k0 < DD; k0 += 8) {
        float4 av = *(const float4*)(Aptr + k0);
        float4 bv = *(const float4*)(Bptr + k0);
        As[loadCol + 0][loadRow] = av.x;
        As[loadCol + 1][loadRow] = av.y;
        As[loadCol + 2][loadRow] = av.z;
        As[loadCol + 3][loadRow] = av.w;
        Bs[loadCol + 0][loadRow] = bv.x;
        Bs[loadCol + 1][loadRow] = bv.y;
        Bs[loadCol + 2][loadRow] = bv.z;
        Bs[loadCol + 3][loadRow] = bv.w;
        __syncthreads();
#pragma unroll
        for (int kk = 0; kk < 8; kk++) {
            float4 a0 = *(const float4*)&As[kk][ty * 8];
            float4 a1 = *(const float4*)&As[kk][ty * 8 + 4];
            ulonglong2 b0 = *(const ulonglong2*)&Bs[kk][tx * 8];
            ulonglong2 b1 = *(const ulonglong2*)&Bs[kk][tx * 8 + 4];
            float a[8] = {a0.x, a0.y, a0.z, a0.w, a1.x, a1.y, a1.z, a1.w};
#pragma unroll
            for (int i = 0; i < 8; i++) {
                unsigned long long ad = dup2(a[i]);
                acc[i][0] = fma2(ad, b0.x, acc[i][0]);
                acc[i][1] = fma2(ad, b0.y, acc[i][1]);
                acc[i][2] = fma2(ad, b1.x, acc[i][2]);
                acc[i][3] = fma2(ad, b1.y, acc[i][3]);
            }
        }
        __syncthreads();
    }

    const int row0 = by * 128 + ty * 8;
    const int col0 = bx * 128 + tx * 8;
    const float* mrow = mask + (size_t)b * SS * SS;
    float* srow = g_scores + (size_t)z * SS * SS;
#pragma unroll
    for (int i = 0; i < 8; i++) {
        size_t roff = (size_t)(row0 + i) * SS;
#pragma unroll
        for (int p = 0; p < 4; p++) {
            float2 v = unpack2(acc[i][p]);
            int c = col0 + p * 2;
            srow[roff + c]     = v.x + mrow[roff + c];
            srow[roff + c + 1] = v.y + mrow[roff + c + 1];
        }
    }
}

// =====================================================================================
// Kernel 3: row softmax (unchanged, passing)
// =====================================================================================
__global__ __launch_bounds__(256)
void softmax_kernel()
{
    __shared__ float red[256];
    const int t = threadIdx.x;
    float* row = g_scores + (size_t)blockIdx.x * SS;

    float4 v = ((const float4*)row)[t];
    float m = fmaxf(fmaxf(v.x, v.y), fmaxf(v.z, v.w));
    red[t] = m;
    __syncthreads();
    for (int s = 128; s > 0; s >>= 1) {
        if (t < s) red[t] = fmaxf(red[t], red[t + s]);
        __syncthreads();
    }
    const float mx = red[0];
    __syncthreads();

    float4 e;
    e.x = expf(v.x - mx);
    e.y = expf(v.y - mx);
    e.z = expf(v.z - mx);
    e.w = expf(v.w - mx);
    red[t] = e.x + e.y + e.z + e.w;
    __syncthreads();
    for (int s = 128; s > 0; s >>= 1) {
        if (t < s) red[t] += red[t + s];
        __syncthreads();
    }
    const float inv = 1.0f / red[0];

    e.x *= inv; e.y *= inv; e.z *= inv; e.w *= inv;
    ((float4*)row)[t] = e;
}

// =====================================================================================
// Kernel 4: ctx[bh] = P[bh] @ V[bh]  (unchanged, passing)
// =====================================================================================
__global__ __launch_bounds__(128, 2)
void pv_kernel()
{
    __shared__ __align__(16) float As[8][128];
    __shared__ __align__(16) float Bs[8][64];

    const int t  = threadIdx.x;
    const int by = blockIdx.x, z = blockIdx.y;
    const int b  = z >> 5, h = z & 31;

    const float* P = g_scores + (size_t)z * SS * SS;
    const float* V = g_v      + (size_t)z * SS * DD;

    const int r0  = t >> 1;
    const int cg  = (t & 1) * 4;
    const int bkr = t >> 4;
    const int bkc = (t & 15) * 4;

    const int ty = t >> 3, tx = t & 7;

    unsigned long long acc[8][4];
#pragma unroll
    for (int i = 0; i < 8; i++)
#pragma unroll
        for (int p = 0; p < 4; p++) acc[i][p] = 0ULL;

    for (int k0 = 0; k0 < SS; k0 += 8) {
        float4 a0 = *(const float4*)(P + (size_t)(by * 128 + r0) * SS + k0 + cg);
        float4 a1 = *(const float4*)(P + (size_t)(by * 128 + 64 + r0) * SS + k0 + cg);
        As[cg + 0][r0] = a0.x;  As[cg + 1][r0] = a0.y;
        As[cg + 2][r0] = a0.z;  As[cg + 3][r0] = a0.w;
        As[cg + 0][64 + r0] = a1.x;  As[cg + 1][64 + r0] = a1.y;
        As[cg + 2][64 + r0] = a1.z;  As[cg + 3][64 + r0] = a1.w;
        float4 bv = *(const float4*)(V + (size_t)(k0 + bkr) * DD + bkc);
        *(float4*)&Bs[bkr][bkc] = bv;
        __syncthreads();
#pragma unroll
        for (int kk = 0; kk < 8; kk++) {
            float4 av0 = *(const float4*)&As[kk][ty * 8];
            float4 av1 = *(const float4*)&As[kk][ty * 8 + 4];
            ulonglong2 b0 = *(const ulonglong2*)&Bs[kk][tx * 8];
            ulonglong2 b1 = *(const ulonglong2*)&Bs[kk][tx * 8 + 4];
            float a[8] = {av0.x, av0.y, av0.z, av0.w, av1.x, av1.y, av1.z, av1.w};
#pragma unroll
            for (int i = 0; i < 8; i++) {
                unsigned long long ad = dup2(a[i]);
                acc[i][0] = fma2(ad, b0.x, acc[i][0]);
                acc[i][1] = fma2(ad, b0.y, acc[i][1]);
                acc[i][2] = fma2(ad, b1.x, acc[i][2]);
                acc[i][3] = fma2(ad, b1.y, acc[i][3]);
            }
        }
        __syncthreads();
    }

    const int row0 = by * 128 + ty * 8;
    const int col0 = tx * 8;
#pragma unroll
    for (int i = 0; i < 8; i++) {
        int q = row0 + i;
        float* orow = g_ctx + ((size_t)(b * SS + q)) * EE + h * DD;
#pragma unroll
        for (int p = 0; p < 4; p++) {
            float2 v = unpack2(acc[i][p]);
            int c = col0 + p * 2;
            orow[c]     = v.x;
            orow[c + 1] = v.y;
        }
    }
}

// =====================================================================================
// kernel_launch — metadata order: hidden_states, attention_mask, Wq, bq, Wk, bk,
//                                 Wv, bv, Wo, bo
// =====================================================================================
extern "C" void kernel_launch(void* const* d_in, const int* in_sizes, int n_in,
                              void* d_out, int out_size)
{
    const float* hidden = (const float*)d_in[0];
    const float* mask   = (const float*)d_in[1];
    const float* Wq     = (const float*)d_in[2];
    const float* bq     = (const float*)d_in[3];
    const float* Wk     = (const float*)d_in[4];
    const float* bk     = (const float*)d_in[5];
    const float* Wv     = (const float*)d_in[6];
    const float* bv     = (const float*)d_in[7];
    const float* Wo     = (const float*)d_in[8];
    const float* bo     = (const float*)d_in[9];
    float*       out    = (float*)d_out;

    unsigned short *hidh, *hidl, *wh, *wl, *ctxh, *ctxl;
    cudaGetSymbolAddress((void**)&hidh, g_hidh);
    cudaGetSymbolAddress((void**)&hidl, g_hidl);
    cudaGetSymbolAddress((void**)&wh,   g_wh);
    cudaGetSymbolAddress((void**)&wl,   g_wl);
    cudaGetSymbolAddress((void**)&ctxh, g_ctxh);
    cudaGetSymbolAddress((void**)&ctxl, g_ctxl);
    float* ctx;
    cudaGetSymbolAddress((void**)&ctx, g_ctx);

    const int nh4 = MM * EE / 4;     // hidden / ctx float4 count
    const int nw4 = EE * EE / 4;     // one weight float4 count

    // split-bf16 pre-pass
    cvt_kernel<<<(nh4 + 255) / 256, 256>>>(hidden, hidh, hidl, nh4);
    cvt_kernel<<<(nw4 + 255) / 256, 256>>>(Wq, wh + 0 * (size_t)EE * EE, wl + 0 * (size_t)EE * EE, nw4);
    cvt_kernel<<<(nw4 + 255) / 256, 256>>>(Wk, wh + 1 * (size_t)EE * EE, wl + 1 * (size_t)EE * EE, nw4);
    cvt_kernel<<<(nw4 + 255) / 256, 256>>>(Wv, wh + 2 * (size_t)EE * EE, wl + 2 * (size_t)EE * EE, nw4);
    cvt_kernel<<<(nw4 + 255) / 256, 256>>>(Wo, wh + 3 * (size_t)EE * EE, wl + 3 * (size_t)EE * EE, nw4);

    // QKV projections on tensor cores (HMMA)
    mma_proj_kernel<<<dim3(EE / 128, MM / 128, 3), 256>>>(
        hidh, hidl, wh, wl, bq, bk, bv, nullptr, 0);

    scores_kernel<<<dim3(SS / 128, SS / 128, BB * HH), 256>>>(mask);
    softmax_kernel<<<BB * HH * SS, 256>>>();
    pv_kernel<<<dim3(SS / 128, BB * HH), 128>>>();

    // Output projection on tensor cores
    cvt_kernel<<<(nh4 + 255) / 256, 256>>>(ctx, ctxh, ctxl, nh4);
    mma_proj_kernel<<<dim3(EE / 128, MM / 128, 1), 256>>>(
        ctxh, ctxl, wh + 3 * (size_t)EE * EE, wl + 3 * (size_t)EE * EE,
        bo, nullptr, nullptr, out, 1);
}

// round 7
// speedup vs baseline: 1.5332x; 1.1072x over previous
#include <cuda_runtime.h>
#include <cuda_bf16.h>

// Problem constants
#define BB 4
#define SS 1024
#define EE 2048
#define HH 32
#define DD 64
#define MM 4096   // BB*SS

// ---------------- device scratch (allocation-free rule: __device__ globals) ----------------
__device__ float g_q[BB*HH*SS*DD];            // (B,H,S,D)
__device__ float g_k[BB*HH*SS*DD];
__device__ float g_v[BB*HH*SS*DD];
__device__ float g_ctx[MM*EE];                // (B,S,E)
__device__ float g_scores[134217728];         // (B*H,S,S)
// split-bf16 planes (bit patterns held as ushort)
__device__ __align__(16) unsigned short g_hidh[MM*EE], g_hidl[MM*EE];
__device__ __align__(16) unsigned short g_wh[4*EE*EE], g_wl[4*EE*EE];
__device__ __align__(16) unsigned short g_ctxh[MM*EE], g_ctxl[MM*EE];

// ---------------- packed f32x2 helpers (attention-middle kernels) ----------------
__device__ __forceinline__ unsigned long long dup2(float a) {
    unsigned long long r;
    asm("mov.b64 %0, {%1, %1};" : "=l"(r) : "f"(a));
    return r;
}
__device__ __forceinline__ unsigned long long fma2(unsigned long long a, unsigned long long b,
                                                   unsigned long long c) {
    unsigned long long d;
    asm("fma.rn.f32x2 %0, %1, %2, %3;" : "=l"(d) : "l"(a), "l"(b), "l"(c));
    return d;
}
__device__ __forceinline__ float2 unpack2(unsigned long long v) {
    float lo, hi;
    asm("mov.b64 {%0, %1}, %2;" : "=f"(lo), "=f"(hi) : "l"(v));
    return make_float2(lo, hi);
}

// ---------------- bf16 bit helpers ----------------
__device__ __forceinline__ unsigned short f2bf(float x) {
    unsigned short r;
    asm("cvt.rn.bf16.f32 %0, %1;" : "=h"(r) : "f"(x));
    return r;
}
__device__ __forceinline__ float bf2f(unsigned short u) {
    return __uint_as_float(((unsigned)u) << 16);
}
__device__ __forceinline__ unsigned smem_u32(const void* p) {
    unsigned a;
    asm("{ .reg .u64 t; cvta.to.shared.u64 t, %1; cvt.u32.u64 %0, t; }" : "=r"(a) : "l"(p));
    return a;
}

// ---------------- mma.sync / ldmatrix / cp.async (family-common at sm_103) ----------------
#define LDSM4(r0, r1, r2, r3, addr)                                             \
    asm volatile("ldmatrix.sync.aligned.m8n8.x4.shared.b16 {%0,%1,%2,%3}, [%4];" \
                 : "=r"(r0), "=r"(r1), "=r"(r2), "=r"(r3) : "r"(addr))

#define MMA16816(d, a0, a1, a2, a3, b0, b1)                                        \
    asm volatile("mma.sync.aligned.m16n8k16.row.col.f32.bf16.bf16.f32 "            \
                 "{%0,%1,%2,%3}, {%4,%5,%6,%7}, {%8,%9}, {%0,%1,%2,%3};"           \
                 : "+f"(d[0]), "+f"(d[1]), "+f"(d[2]), "+f"(d[3])                  \
                 : "r"(a0), "r"(a1), "r"(a2), "r"(a3), "r"(b0), "r"(b1))

#define CP16(dst, src) \
    asm volatile("cp.async.cg.shared.global [%0], [%1], 16;" :: "r"(dst), "l"(src))
#define CP_COMMIT() asm volatile("cp.async.commit_group;" ::: "memory")
#define CP_WAIT1()  asm volatile("cp.async.wait_group 1;" ::: "memory")
#define CP_WAIT0()  asm volatile("cp.async.wait_group 0;" ::: "memory")

// =====================================================================================
// Pre-pass: fp32 -> (hi, lo) bf16 planes.  x = bf16(x) + bf16(x - bf16(x)) + O(u^2).
// =====================================================================================
__global__ __launch_bounds__(256)
void cvt_kernel(const float* __restrict__ src, unsigned short* __restrict__ hi,
                unsigned short* __restrict__ lo, int n4)
{
    int i = blockIdx.x * 256 + threadIdx.x;
    if (i >= n4) return;
    float4 v = ((const float4*)src)[i];
    unsigned short hx = f2bf(v.x), hy = f2bf(v.y), hz = f2bf(v.z), hw = f2bf(v.w);
    unsigned short lx = f2bf(v.x - bf2f(hx)), ly = f2bf(v.y - bf2f(hy));
    unsigned short lz = f2bf(v.z - bf2f(hz)), lw = f2bf(v.w - bf2f(hw));
    ((uint2*)hi)[i] = make_uint2((unsigned)hx | ((unsigned)hy << 16),
                                 (unsigned)hz | ((unsigned)hw << 16));
    ((uint2*)lo)[i] = make_uint2((unsigned)lx | ((unsigned)ly << 16),
                                 (unsigned)lz | ((unsigned)lw << 16));
}

// =====================================================================================
// Tensor-core projection GEMM (HMMA + cp.async double buffering).
// C[128x128] = A[128xK] @ W[128xK]^T via split-bf16 (AhBh + AhBl + AlBh), fp32 accum.
// CTA 128x128, 256 threads = 8 warps (2m x 4n), warp tile 64x32, k-chunk 32, 2 stages.
// =====================================================================================
#define SPAD 40                     // smem row stride in bf16 elems
#define TILE_E (128 * SPAD)         // ushort elems per tile
#define TILE_B (TILE_E * 2)         // 10240 bytes per tile
#define PROJ_DSM (2 * 4 * TILE_B)   // 81920 bytes

__global__ __launch_bounds__(256, 1)
void mma_proj_kernel(const unsigned short* __restrict__ Ah,
                     const unsigned short* __restrict__ Al,
                     const unsigned short* __restrict__ Whb,
                     const unsigned short* __restrict__ Wlb,
                     const float* __restrict__ b0, const float* __restrict__ b1,
                     const float* __restrict__ b2,
                     float* __restrict__ flat_out, int flat)
{
    extern __shared__ __align__(16) char dsm[];

    const int t    = threadIdx.x;
    const int lane = t & 31;
    const int wid  = t >> 5;
    const int wm   = wid >> 2;          // 0..1
    const int wn   = wid & 3;           // 0..3
    const int bx = blockIdx.x, by = blockIdx.y, z = blockIdx.z;

    const unsigned short* Wh = Whb + (size_t)z * EE * EE;
    const unsigned short* Wl = Wlb + (size_t)z * EE * EE;
    const float* bias = (z == 0) ? b0 : (z == 1) ? b1 : b2;
    float*       outp = (z == 0) ? g_q : (z == 1) ? g_k : g_v;
    const float scale = (flat == 0 && z == 0) ? 0.125f : 1.0f;

    const int m0 = by * 128, n0 = bx * 128;
    const unsigned sbase = smem_u32(dsm);

    float acc[4][4][4];
#pragma unroll
    for (int i = 0; i < 4; i++)
#pragma unroll
        for (int j = 0; j < 4; j++)
#pragma unroll
            for (int p = 0; p < 4; p++) acc[i][j][p] = 0.0f;

    // per-thread load geometry: 2 uint4 per array per chunk
    const int u0   = t * 2;
    const int row0l = u0 >> 2;
    const int cq0   = (u0 & 3) * 8;
    const int row1l = (u0 + 1) >> 2;
    const int cq1   = ((u0 + 1) & 3) * 8;

    // ldmatrix source geometry
    const int a_row = wm * 64 + ((lane >> 3) & 1) * 8 + (lane & 7);
    const int a_co  = ((lane >> 4) & 1) * 8;
    const int b_row = wn * 32 + ((lane >> 4) & 1) * 8 + (lane & 7);
    const int b_co  = ((lane >> 3) & 1) * 8;
    // per-stage tile base byte offsets: stage*4 tiles + {0:Ah,1:Al,2:Bh,3:Bl}
    unsigned aAh[2], aAl[2], aBh[2], aBl[2];
#pragma unroll
    for (int s = 0; s < 2; s++) {
        const unsigned sb = sbase + (unsigned)(s * 4 * TILE_B);
        aAh[s] = sb + 0 * TILE_B + (unsigned)((a_row * SPAD + a_co) * 2);
        aAl[s] = sb + 1 * TILE_B + (unsigned)((a_row * SPAD + a_co) * 2);
        aBh[s] = sb + 2 * TILE_B + (unsigned)((b_row * SPAD + b_co) * 2);
        aBl[s] = sb + 3 * TILE_B + (unsigned)((b_row * SPAD + b_co) * 2);
    }

    // issue async loads of one k-chunk into stage s
    auto issue_loads = [&](int s, int k0) {
        const unsigned sb = sbase + (unsigned)(s * 4 * TILE_B);
        const unsigned d0 = (unsigned)((row0l * SPAD + cq0) * 2);
        const unsigned d1 = (unsigned)((row1l * SPAD + cq1) * 2);
        const size_t a0 = (size_t)(m0 + row0l) * EE + k0 + cq0;
        const size_t a1 = (size_t)(m0 + row1l) * EE + k0 + cq1;
        const size_t b0i = (size_t)(n0 + row0l) * EE + k0 + cq0;
        const size_t b1i = (size_t)(n0 + row1l) * EE + k0 + cq1;
        CP16(sb + 0 * TILE_B + d0, Ah + a0);
        CP16(sb + 0 * TILE_B + d1, Ah + a1);
        CP16(sb + 1 * TILE_B + d0, Al + a0);
        CP16(sb + 1 * TILE_B + d1, Al + a1);
        CP16(sb + 2 * TILE_B + d0, Wh + b0i);
        CP16(sb + 2 * TILE_B + d1, Wh + b1i);
        CP16(sb + 3 * TILE_B + d0, Wl + b0i);
        CP16(sb + 3 * TILE_B + d1, Wl + b1i);
    };

    const int NCH = EE / 32;
    issue_loads(0, 0);
    CP_COMMIT();

#pragma unroll 1
    for (int ch = 0; ch < NCH; ch++) {
        const int buf = ch & 1;
        if (ch + 1 < NCH) {
            issue_loads(buf ^ 1, (ch + 1) * 32);
            CP_COMMIT();
            CP_WAIT1();
        } else {
            CP_WAIT0();
        }
        __syncthreads();

#pragma unroll
        for (int kk2 = 0; kk2 < 2; kk2++) {
            const unsigned ko = (unsigned)(kk2 * 16 * 2);
            unsigned ah[4][4], al[4][4], bh[2][4], bl[2][4];
#pragma unroll
            for (int mt = 0; mt < 4; mt++) {
                const unsigned off = (unsigned)(mt * 16 * SPAD * 2) + ko;
                LDSM4(ah[mt][0], ah[mt][1], ah[mt][2], ah[mt][3], aAh[buf] + off);
                LDSM4(al[mt][0], al[mt][1], al[mt][2], al[mt][3], aAl[buf] + off);
            }
#pragma unroll
            for (int np = 0; np < 2; np++) {
                const unsigned off = (unsigned)(np * 16 * SPAD * 2) + ko;
                LDSM4(bh[np][0], bh[np][1], bh[np][2], bh[np][3], aBh[buf] + off);
                LDSM4(bl[np][0], bl[np][1], bl[np][2], bl[np][3], aBl[buf] + off);
            }
#pragma unroll
            for (int mt = 0; mt < 4; mt++) {
#pragma unroll
                for (int np = 0; np < 2; np++) {
#pragma unroll
                    for (int hf = 0; hf < 2; hf++) {
                        const int nt = np * 2 + hf;
                        const unsigned B0h = bh[np][hf * 2], B1h = bh[np][hf * 2 + 1];
                        const unsigned B0l = bl[np][hf * 2], B1l = bl[np][hf * 2 + 1];
                        MMA16816(acc[mt][nt], ah[mt][0], ah[mt][1], ah[mt][2], ah[mt][3], B0h, B1h);
                        MMA16816(acc[mt][nt], ah[mt][0], ah[mt][1], ah[mt][2], ah[mt][3], B0l, B1l);
                        MMA16816(acc[mt][nt], al[mt][0], al[mt][1], al[mt][2], al[mt][3], B0h, B1h);
                    }
                }
            }
        }
        __syncthreads();
    }

    // ---- epilogue: D fragment rows = lane>>2 (+8), cols = (lane&3)*2 (+1) ----
    const int erow = lane >> 2;
    const int ecol = (lane & 3) * 2;
#pragma unroll
    for (int mt = 0; mt < 4; mt++) {
#pragma unroll
        for (int nt = 0; nt < 4; nt++) {
            const int m = m0 + wm * 64 + mt * 16 + erow;
            const int n = n0 + wn * 32 + nt * 8 + ecol;
            const float bz0 = bias[n], bz1 = bias[n + 1];
            if (flat) {
                float* p0 = flat_out + (size_t)m * EE + n;
                float* p1 = flat_out + (size_t)(m + 8) * EE + n;
                p0[0] = acc[mt][nt][0] + bz0;
                p0[1] = acc[mt][nt][1] + bz1;
                p1[0] = acc[mt][nt][2] + bz0;
                p1[1] = acc[mt][nt][3] + bz1;
            } else {
                const int h = n >> 6, d = n & 63;
                const int b0i = m >> 10, s0 = m & 1023;
                const int b1i = (m + 8) >> 10, s1 = (m + 8) & 1023;
                float* p0 = outp + ((size_t)(b0i * HH + h) * SS + s0) * DD + d;
                float* p1 = outp + ((size_t)(b1i * HH + h) * SS + s1) * DD + d;
                p0[0] = (acc[mt][nt][0] + bz0) * scale;
                p0[1] = (acc[mt][nt][1] + bz1) * scale;
                p1[0] = (acc[mt][nt][2] + bz0) * scale;
                p1[1] = (acc[mt][nt][3] + bz1) * scale;
            }
        }
    }
}

// =====================================================================================
// Kernel 2: scores[bh] = Q[bh] @ K[bh]^T + mask[b]  (unchanged, passing)
// =====================================================================================
__global__ __launch_bounds__(256, 2)
void scores_kernel(const float* __restrict__ mask)
{
    __shared__ __align__(16) float As[8][128];
    __shared__ __align__(16) float Bs[8][128];

    const int t  = threadIdx.x;
    const int bx = blockIdx.x, by = blockIdx.y, z = blockIdx.z;
    const int b  = z >> 5;

    const float* Qb = g_q + (size_t)z * SS * DD;
    const float* Kb = g_k + (size_t)z * SS * DD;

    const int loadRow = t >> 1;
    const int loadCol = (t & 1) * 4;
    const float* Aptr = Qb + (size_t)(by * 128 + loadRow) * DD + loadCol;
    const float* Bptr = Kb + (size_t)(bx * 128 + loadRow) * DD + loadCol;

    const int ty = t >> 4, tx = t & 15;

    unsigned long long acc[8][4];
#pragma unroll
    for (int i = 0; i < 8; i++)
#pragma unroll
        for (int p = 0; p < 4; p++) acc[i][p] = 0ULL;

#pragma unroll 1
    for (int k0 = 0; k0 < DD; k0 += 8) {
        float4 av = *(const float4*)(Aptr + k0);
        float4 bv = *(const float4*)(Bptr + k0);
        As[loadCol + 0][loadRow] = av.x;
        As[loadCol + 1][loadRow] = av.y;
        As[loadCol + 2][loadRow] = av.z;
        As[loadCol + 3][loadRow] = av.w;
        Bs[loadCol + 0][loadRow] = bv.x;
        Bs[loadCol + 1][loadRow] = bv.y;
        Bs[loadCol + 2][loadRow] = bv.z;
        Bs[loadCol + 3][loadRow] = bv.w;
        __syncthreads();
#pragma unroll
        for (int kk = 0; kk < 8; kk++) {
            float4 a0 = *(const float4*)&As[kk][ty * 8];
            float4 a1 = *(const float4*)&As[kk][ty * 8 + 4];
            ulonglong2 b0 = *(const ulonglong2*)&Bs[kk][tx * 8];
            ulonglong2 b1 = *(const ulonglong2*)&Bs[kk][tx * 8 + 4];
            float a[8] = {a0.x, a0.y, a0.z, a0.w, a1.x, a1.y, a1.z, a1.w};
#pragma unroll
            for (int i = 0; i < 8; i++) {
                unsigned long long ad = dup2(a[i]);
                acc[i][0] = fma2(ad, b0.x, acc[i][0]);
                acc[i][1] = fma2(ad, b0.y, acc[i][1]);
                acc[i][2] = fma2(ad, b1.x, acc[i][2]);
                acc[i][3] = fma2(ad, b1.y, acc[i][3]);
            }
        }
        __syncthreads();
    }

    const int row0 = by * 128 + ty * 8;
    const int col0 = bx * 128 + tx * 8;
    const float* mrow = mask + (size_t)b * SS * SS;
    float* srow = g_scores + (size_t)z * SS * SS;
#pragma unroll
    for (int i = 0; i < 8; i++) {
        size_t roff = (size_t)(row0 + i) * SS;
#pragma unroll
        for (int p = 0; p < 4; p++) {
            float2 v = unpack2(acc[i][p]);
            int c = col0 + p * 2;
            srow[roff + c]     = v.x + mrow[roff + c];
            srow[roff + c + 1] = v.y + mrow[roff + c + 1];
        }
    }
}

// =====================================================================================
// Kernel 3: row softmax (unchanged, passing)
// =====================================================================================
__global__ __launch_bounds__(256)
void softmax_kernel()
{
    __shared__ float red[256];
    const int t = threadIdx.x;
    float* row = g_scores + (size_t)blockIdx.x * SS;

    float4 v = ((const float4*)row)[t];
    float m = fmaxf(fmaxf(v.x, v.y), fmaxf(v.z, v.w));
    red[t] = m;
    __syncthreads();
    for (int s = 128; s > 0; s >>= 1) {
        if (t < s) red[t] = fmaxf(red[t], red[t + s]);
        __syncthreads();
    }
    const float mx = red[0];
    __syncthreads();

    float4 e;
    e.x = expf(v.x - mx);
    e.y = expf(v.y - mx);
    e.z = expf(v.z - mx);
    e.w = expf(v.w - mx);
    red[t] = e.x + e.y + e.z + e.w;
    __syncthreads();
    for (int s = 128; s > 0; s >>= 1) {
        if (t < s) red[t] += red[t + s];
        __syncthreads();
    }
    const float inv = 1.0f / red[0];

    e.x *= inv; e.y *= inv; e.z *= inv; e.w *= inv;
    ((float4*)row)[t] = e;
}

// =====================================================================================
// Kernel 4: ctx[bh] = P[bh] @ V[bh]  (unchanged, passing)
// =====================================================================================
__global__ __launch_bounds__(128, 2)
void pv_kernel()
{
    __shared__ __align__(16) float As[8][128];
    __shared__ __align__(16) float Bs[8][64];

    const int t  = threadIdx.x;
    const int by = blockIdx.x, z = blockIdx.y;
    const int b  = z >> 5, h = z & 31;

    const float* P = g_scores + (size_t)z * SS * SS;
    const float* V = g_v      + (size_t)z * SS * DD;

    const int r0  = t >> 1;
    const int cg  = (t & 1) * 4;
    const int bkr = t >> 4;
    const int bkc = (t & 15) * 4;

    const int ty = t >> 3, tx = t & 7;

    unsigned long long acc[8][4];
#pragma unroll
    for (int i = 0; i < 8; i++)
#pragma unroll
        for (int p = 0; p < 4; p++) acc[i][p] = 0ULL;

    for (int k0 = 0; k0 < SS; k0 += 8) {
        float4 a0 = *(const float4*)(P + (size_t)(by * 128 + r0) * SS + k0 + cg);
        float4 a1 = *(const float4*)(P + (size_t)(by * 128 + 64 + r0) * SS + k0 + cg);
        As[cg + 0][r0] = a0.x;  As[cg + 1][r0] = a0.y;
        As[cg + 2][r0] = a0.z;  As[cg + 3][r0] = a0.w;
        As[cg + 0][64 + r0] = a1.x;  As[cg + 1][64 + r0] = a1.y;
        As[cg + 2][64 + r0] = a1.z;  As[cg + 3][64 + r0] = a1.w;
        float4 bv = *(const float4*)(V + (size_t)(k0 + bkr) * DD + bkc);
        *(float4*)&Bs[bkr][bkc] = bv;
        __syncthreads();
#pragma unroll
        for (int kk = 0; kk < 8; kk++) {
            float4 av0 = *(const float4*)&As[kk][ty * 8];
            float4 av1 = *(const float4*)&As[kk][ty * 8 + 4];
            ulonglong2 b0 = *(const ulonglong2*)&Bs[kk][tx * 8];
            ulonglong2 b1 = *(const ulonglong2*)&Bs[kk][tx * 8 + 4];
            float a[8] = {av0.x, av0.y, av0.z, av0.w, av1.x, av1.y, av1.z, av1.w};
#pragma unroll
            for (int i = 0; i < 8; i++) {
                unsigned long long ad = dup2(a[i]);
                acc[i][0] = fma2(ad, b0.x, acc[i][0]);
                acc[i][1] = fma2(ad, b0.y, acc[i][1]);
                acc[i][2] = fma2(ad, b1.x, acc[i][2]);
                acc[i][3] = fma2(ad, b1.y, acc[i][3]);
            }
        }
        __syncthreads();
    }

    const int row0 = by * 128 + ty * 8;
    const int col0 = tx * 8;
#pragma unroll
    for (int i = 0; i < 8; i++) {
        int q = row0 + i;
        float* orow = g_ctx + ((size_t)(b * SS + q)) * EE + h * DD;
#pragma unroll
        for (int p = 0; p < 4; p++) {
            float2 v = unpack2(acc[i][p]);
            int c = col0 + p * 2;
            orow[c]     = v.x;
            orow[c + 1] = v.y;
        }
    }
}

// =====================================================================================
// kernel_launch — metadata order: hidden_states, attention_mask, Wq, bq, Wk, bk,
//                                 Wv, bv, Wo, bo
// =====================================================================================
extern "C" void kernel_launch(void* const* d_in, const int* in_sizes, int n_in,
                              void* d_out, int out_size)
{
    const float* hidden = (const float*)d_in[0];
    const float* mask   = (const float*)d_in[1];
    const float* Wq     = (const float*)d_in[2];
    const float* bq     = (const float*)d_in[3];
    const float* Wk     = (const float*)d_in[4];
    const float* bk     = (const float*)d_in[5];
    const float* Wv     = (const float*)d_in[6];
    const float* bv     = (const float*)d_in[7];
    const float* Wo     = (const float*)d_in[8];
    const float* bo     = (const float*)d_in[9];
    float*       out    = (float*)d_out;

    unsigned short *hidh, *hidl, *wh, *wl, *ctxh, *ctxl;
    cudaGetSymbolAddress((void**)&hidh, g_hidh);
    cudaGetSymbolAddress((void**)&hidl, g_hidl);
    cudaGetSymbolAddress((void**)&wh,   g_wh);
    cudaGetSymbolAddress((void**)&wl,   g_wl);
    cudaGetSymbolAddress((void**)&ctxh, g_ctxh);
    cudaGetSymbolAddress((void**)&ctxl, g_ctxl);
    float* ctx;
    cudaGetSymbolAddress((void**)&ctx, g_ctx);

    cudaFuncSetAttribute(mma_proj_kernel, cudaFuncAttributeMaxDynamicSharedMemorySize, PROJ_DSM);

    const int nh4 = MM * EE / 4;     // hidden / ctx float4 count
    const int nw4 = EE * EE / 4;     // one weight float4 count

    // split-bf16 pre-pass
    cvt_kernel<<<(nh4 + 255) / 256, 256>>>(hidden, hidh, hidl, nh4);
    cvt_kernel<<<(nw4 + 255) / 256, 256>>>(Wq, wh + 0 * (size_t)EE * EE, wl + 0 * (size_t)EE * EE, nw4);
    cvt_kernel<<<(nw4 + 255) / 256, 256>>>(Wk, wh + 1 * (size_t)EE * EE, wl + 1 * (size_t)EE * EE, nw4);
    cvt_kernel<<<(nw4 + 255) / 256, 256>>>(Wv, wh + 2 * (size_t)EE * EE, wl + 2 * (size_t)EE * EE, nw4);
    cvt_kernel<<<(nw4 + 255) / 256, 256>>>(Wo, wh + 3 * (size_t)EE * EE, wl + 3 * (size_t)EE * EE, nw4);

    // QKV projections on tensor cores (HMMA, double-buffered cp.async)
    mma_proj_kernel<<<dim3(EE / 128, MM / 128, 3), 256, PROJ_DSM>>>(
        hidh, hidl, wh, wl, bq, bk, bv, nullptr, 0);

    scores_kernel<<<dim3(SS / 128, SS / 128, BB * HH), 256>>>(mask);
    softmax_kernel<<<BB * HH * SS, 256>>>();
    pv_kernel<<<dim3(SS / 128, BB * HH), 128>>>();

    // Output projection on tensor cores
    cvt_kernel<<<(nh4 + 255) / 256, 256>>>(ctx, ctxh, ctxl, nh4);
    mma_proj_kernel<<<dim3(EE / 128, MM / 128, 1), 256, PROJ_DSM>>>(
        ctxh, ctxl, wh + 3 * (size_t)EE * EE, wl + 3 * (size_t)EE * EE,
        bo, nullptr, nullptr, out, 1);
}